// round 2
// baseline (speedup 1.0000x reference)
#include <cuda_runtime.h>
#include <math.h>

#define BLOCK_THREADS 128
#define NPAIR 4                                   // 8 dirs/thread as 4 f32x2 pairs
#define DIRS_PER_BLOCK (BLOCK_THREADS * 2 * NPAIR)
#define MAX_COMP 128

typedef unsigned long long u64;

__device__ __forceinline__ u64 pk2(float lo, float hi) {
    u64 r; asm("mov.b64 %0, {%1, %2};" : "=l"(r) : "f"(lo), "f"(hi)); return r;
}
__device__ __forceinline__ void unpk2(u64 v, float& lo, float& hi) {
    asm("mov.b64 {%0, %1}, %2;" : "=f"(lo), "=f"(hi) : "l"(v));
}
__device__ __forceinline__ u64 ffma2(u64 a, u64 b, u64 c) {
    u64 r; asm("fma.rn.f32x2 %0, %1, %2, %3;" : "=l"(r) : "l"(a), "l"(b), "l"(c)); return r;
}
__device__ __forceinline__ u64 fadd2(u64 a, u64 b) {
    u64 r; asm("add.rn.f32x2 %0, %1, %2;" : "=l"(r) : "l"(a), "l"(b)); return r;
}
__device__ __forceinline__ float ex2a(float x) {
    float r; asm("ex2.approx.ftz.f32 %0, %1;" : "=f"(r) : "f"(x)); return r;
}

__global__ void __launch_bounds__(BLOCK_THREADS)
vmf_mixture_kernel(const float* __restrict__ lambdas,
                   const float* __restrict__ kappas,
                   const float* __restrict__ thetas,
                   const float* __restrict__ phis,
                   const float* __restrict__ wi,
                   float* __restrict__ out,
                   int S, int N)
{
    // per component: {ax,ax},{ay,ay},{az,az},{b,b} pre-broadcast f32x2
    __shared__ u64 sPK[MAX_COMP][4];

    int t = threadIdx.x;
    if (t < N) {
        float kappa = kappas[t];
        float lam   = lambdas[t];
        float th    = thetas[t];
        float ph    = phis[t];

        float st = sinf(th), ct = cosf(th);
        float sp = sinf(ph), cp = cosf(ph);

        float k = fmaxf(kappa, 1e-8f);
        float norm = (kappa < 1e-5f)
                   ? 0.07957747154594767f                       // 1/(4pi)
                   : k * 0.15915494309189535f / (1.0f - expf(-2.0f * k));
        float c = lam * norm;                                   // > 0 always

        const float LOG2E = 1.4426950408889634f;
        float a  = kappa * LOG2E;
        float b  = log2f(c) - a;                                // fold weight into exponent
        float ax = a * (st * cp), ay = a * (st * sp), az = a * ct;

        sPK[t][0] = pk2(ax, ax);
        sPK[t][1] = pk2(ay, ay);
        sPK[t][2] = pk2(az, az);
        sPK[t][3] = pk2(b,  b);
    }
    __syncthreads();

    int base = blockIdx.x * DIRS_PER_BLOCK + t;

    u64 X[NPAIR], Y[NPAIR], Z[NPAIR], ACC[NPAIR];
    #pragma unroll
    for (int j = 0; j < NPAIR; j++) {
        int i0 = base + (2 * j)     * BLOCK_THREADS;
        int i1 = base + (2 * j + 1) * BLOCK_THREADS;
        int o0 = (i0 < S) ? 3 * i0 : 0;
        int o1 = (i1 < S) ? 3 * i1 : 0;
        X[j] = pk2(wi[o0 + 0], wi[o1 + 0]);
        Y[j] = pk2(wi[o0 + 1], wi[o1 + 1]);
        Z[j] = pk2(wi[o0 + 2], wi[o1 + 2]);
        ACC[j] = 0ull;
    }

    // packed constants for software exp2 (registers, loop invariant)
    const u64 MAGIC2  = pk2( 12582912.0f,  12582912.0f);   // 1.5*2^23: round-to-int magic
    const u64 NMAGIC2 = pk2(-12582912.0f, -12582912.0f);
    const u64 NEG1_2  = pk2(-1.0f, -1.0f);
    const u64 C0_2 = pk2(1.0f,                  1.0f);
    const u64 C1_2 = pk2(0.6931471805599453f,   0.6931471805599453f);
    const u64 C2_2 = pk2(0.2402265069591007f,   0.2402265069591007f);
    const u64 C3_2 = pk2(0.05550410866482158f,  0.05550410866482158f);
    const u64 C4_2 = pk2(0.009618129107628477f, 0.009618129107628477f);
    const int MCLAMP_BITS = __float_as_int(12582912.0f - 124.0f); // clamp n >= -124

    #pragma unroll 1
    for (int n = 0; n < N; n++) {
        u64 ax2 = sPK[n][0];
        u64 ay2 = sPK[n][1];
        u64 az2 = sPK[n][2];
        u64 b2  = sPK[n][3];

        // 3 pairs (6 dirs) via MUFU.EX2
        #pragma unroll
        for (int j = 0; j < NPAIR - 1; j++) {
            u64 arg = ffma2(az2, Z[j], b2);
            arg = ffma2(ay2, Y[j], arg);
            arg = ffma2(ax2, X[j], arg);
            float alo, ahi; unpk2(arg, alo, ahi);
            ACC[j] = fadd2(ACC[j], pk2(ex2a(alo), ex2a(ahi)));
        }

        // 1 pair (2 dirs) via packed software exp2 on FMA/ALU pipes
        {
            u64 arg = ffma2(az2, Z[NPAIR - 1], b2);
            arg = ffma2(ay2, Y[NPAIR - 1], arg);
            arg = ffma2(ax2, X[NPAIR - 1], arg);

            u64 m2 = fadd2(arg, MAGIC2);        // m = round(arg) + magic (bits hold n)
            u64 n2 = fadd2(m2, NMAGIC2);        // n = round(arg) as float
            u64 r2 = ffma2(n2, NEG1_2, arg);    // r = arg - n,  r in [-0.5, 0.5]
            u64 p2 = ffma2(C4_2, r2, C3_2);     // poly(r) ~= 2^r
            p2 = ffma2(p2, r2, C2_2);
            p2 = ffma2(p2, r2, C1_2);
            p2 = ffma2(p2, r2, C0_2);

            float mlo, mhi, plo, phi_;
            unpk2(m2, mlo, mhi);
            unpk2(p2, plo, phi_);
            int il = max(__float_as_int(mlo), MCLAMP_BITS);
            int ih = max(__float_as_int(mhi), MCLAMP_BITS);
            // splice exponent: bits(poly) + (n << 23); (n mod 512)<<23 is exact 2's-comp
            int el = __float_as_int(plo)  + (il << 23);
            int eh = __float_as_int(phi_) + (ih << 23);
            ACC[NPAIR - 1] = fadd2(ACC[NPAIR - 1],
                                   pk2(__int_as_float(el), __int_as_float(eh)));
        }
    }

    #pragma unroll
    for (int j = 0; j < NPAIR; j++) {
        float a0, a1; unpk2(ACC[j], a0, a1);
        int i0 = base + (2 * j) * BLOCK_THREADS;
        int i1 = i0 + BLOCK_THREADS;
        if (i0 < S) out[i0] = a0;
        if (i1 < S) out[i1] = a1;
    }
}

extern "C" void kernel_launch(void* const* d_in, const int* in_sizes, int n_in,
                              void* d_out, int out_size)
{
    const float* lambdas = (const float*)d_in[0];
    const float* kappas  = (const float*)d_in[1];
    const float* thetas  = (const float*)d_in[2];
    const float* phis    = (const float*)d_in[3];
    const float* wi      = (const float*)d_in[4];
    float* out = (float*)d_out;

    int N = in_sizes[0];
    int S = in_sizes[4] / 3;

    int blocks = (S + DIRS_PER_BLOCK - 1) / DIRS_PER_BLOCK;
    vmf_mixture_kernel<<<blocks, BLOCK_THREADS>>>(lambdas, kappas, thetas, phis, wi,
                                                  out, S, N);
}

// round 3
// speedup vs baseline: 1.1015x; 1.1015x over previous
#include <cuda_runtime.h>
#include <math.h>

#define BLOCK_THREADS 128
#define NPAIR 4                                   // 8 dirs/thread as 4 f32x2 pairs
#define DIRS_PER_BLOCK (BLOCK_THREADS * 2 * NPAIR)
#define MAX_COMP 64

typedef unsigned long long u64;

__device__ __forceinline__ u64 pk2(float lo, float hi) {
    u64 r; asm("mov.b64 %0, {%1, %2};" : "=l"(r) : "f"(lo), "f"(hi)); return r;
}
__device__ __forceinline__ void unpk2(u64 v, float& lo, float& hi) {
    asm("mov.b64 {%0, %1}, %2;" : "=f"(lo), "=f"(hi) : "l"(v));
}
__device__ __forceinline__ u64 ffma2(u64 a, u64 b, u64 c) {
    u64 r; asm("fma.rn.f32x2 %0, %1, %2, %3;" : "=l"(r) : "l"(a), "l"(b), "l"(c)); return r;
}
__device__ __forceinline__ u64 fadd2(u64 a, u64 b) {
    u64 r; asm("add.rn.f32x2 %0, %1, %2;" : "=l"(r) : "l"(a), "l"(b)); return r;
}
__device__ __forceinline__ float ex2a(float x) {
    float r; asm("ex2.approx.ftz.f32 %0, %1;" : "=f"(r) : "f"(x)); return r;
}

__global__ void __launch_bounds__(BLOCK_THREADS)
vmf_mixture_kernel(const float* __restrict__ lambdas,
                   const float* __restrict__ kappas,
                   const float* __restrict__ thetas,
                   const float* __restrict__ phis,
                   const float* __restrict__ wi,
                   float* __restrict__ out,
                   int S, int N)
{
    // per component: [0]={ {ax,ax},{ay,ay} }  [1]={ {az,az},{b,b} }  (pre-broadcast f32x2)
    __shared__ ulonglong2 sPK[MAX_COMP][2];

    int t = threadIdx.x;
    if (t < N) {
        float kappa = kappas[t];
        float lam   = lambdas[t];
        float th    = thetas[t];
        float ph    = phis[t];

        float st = sinf(th), ct = cosf(th);
        float sp = sinf(ph), cp = cosf(ph);

        float k = fmaxf(kappa, 1e-8f);
        float norm = (kappa < 1e-5f)
                   ? 0.07957747154594767f                       // 1/(4pi)
                   : k * 0.15915494309189535f / (1.0f - expf(-2.0f * k));
        float c = lam * norm;                                   // > 0 always

        const float LOG2E = 1.4426950408889634f;
        float a  = kappa * LOG2E;
        float b  = log2f(c) - a;                                // fold weight into exponent
        float ax = a * (st * cp), ay = a * (st * sp), az = a * ct;

        sPK[t][0] = make_ulonglong2(pk2(ax, ax), pk2(ay, ay));
        sPK[t][1] = make_ulonglong2(pk2(az, az), pk2(b,  b));
    }
    __syncthreads();

    int base = blockIdx.x * DIRS_PER_BLOCK + t;

    u64 X[NPAIR], Y[NPAIR], Z[NPAIR], ACC[NPAIR];
    #pragma unroll
    for (int j = 0; j < NPAIR; j++) {
        int i0 = base + (2 * j)     * BLOCK_THREADS;
        int i1 = base + (2 * j + 1) * BLOCK_THREADS;
        int o0 = (i0 < S) ? 3 * i0 : 0;
        int o1 = (i1 < S) ? 3 * i1 : 0;
        X[j] = pk2(wi[o0 + 0], wi[o1 + 0]);
        Y[j] = pk2(wi[o0 + 1], wi[o1 + 1]);
        Z[j] = pk2(wi[o0 + 2], wi[o1 + 2]);
        ACC[j] = 0ull;
    }

    // packed constants for software exp2 (registers, loop invariant)
    const u64 MAGIC2  = pk2( 12582912.0f,  12582912.0f);   // 1.5*2^23: round-to-int magic
    const u64 NMAGIC2 = pk2(-12582912.0f, -12582912.0f);
    const u64 NEG1_2  = pk2(-1.0f, -1.0f);
    const u64 C0_2 = pk2(1.0f,                  1.0f);
    const u64 C1_2 = pk2(0.6931471805599453f,   0.6931471805599453f);
    const u64 C2_2 = pk2(0.2402265069591007f,   0.2402265069591007f);
    const u64 C3_2 = pk2(0.05550410866482158f,  0.05550410866482158f);
    const u64 C4_2 = pk2(0.009618129107628477f, 0.009618129107628477f);
    const int MCLAMP_BITS = __float_as_int(12582912.0f - 124.0f); // clamp n >= -124

    #pragma unroll 4
    for (int n = 0; n < N; n++) {
        ulonglong2 p0 = sPK[n][0];     // {ax2, ay2}
        ulonglong2 p1 = sPK[n][1];     // {az2, b2 }
        u64 ax2 = p0.x, ay2 = p0.y, az2 = p1.x, b2 = p1.y;

        // 3 pairs (6 dirs) via MUFU.EX2
        #pragma unroll
        for (int j = 0; j < NPAIR - 1; j++) {
            u64 arg = ffma2(az2, Z[j], b2);
            arg = ffma2(ay2, Y[j], arg);
            arg = ffma2(ax2, X[j], arg);
            float alo, ahi; unpk2(arg, alo, ahi);
            ACC[j] = fadd2(ACC[j], pk2(ex2a(alo), ex2a(ahi)));
        }

        // 1 pair (2 dirs) via packed software exp2 on FMA/ALU pipes
        {
            u64 arg = ffma2(az2, Z[NPAIR - 1], b2);
            arg = ffma2(ay2, Y[NPAIR - 1], arg);
            arg = ffma2(ax2, X[NPAIR - 1], arg);

            u64 m2 = fadd2(arg, MAGIC2);        // m bits hold round(arg)
            u64 n2 = fadd2(m2, NMAGIC2);        // n = round(arg) as float
            u64 r2 = ffma2(n2, NEG1_2, arg);    // r = arg - n, in [-0.5, 0.5]
            u64 q2 = ffma2(C4_2, r2, C3_2);     // poly(r) ~= 2^r
            q2 = ffma2(q2, r2, C2_2);
            q2 = ffma2(q2, r2, C1_2);
            q2 = ffma2(q2, r2, C0_2);

            float mlo, mhi, qlo, qhi;
            unpk2(m2, mlo, mhi);
            unpk2(q2, qlo, qhi);
            int il = max(__float_as_int(mlo), MCLAMP_BITS);
            int ih = max(__float_as_int(mhi), MCLAMP_BITS);
            // splice exponent: bits(poly) + (n << 23)  (exact mod 2^32)
            int el = __float_as_int(qlo) + (il << 23);
            int eh = __float_as_int(qhi) + (ih << 23);
            ACC[NPAIR - 1] = fadd2(ACC[NPAIR - 1],
                                   pk2(__int_as_float(el), __int_as_float(eh)));
        }
    }

    #pragma unroll
    for (int j = 0; j < NPAIR; j++) {
        float a0, a1; unpk2(ACC[j], a0, a1);
        int i0 = base + (2 * j) * BLOCK_THREADS;
        int i1 = i0 + BLOCK_THREADS;
        if (i0 < S) out[i0] = a0;
        if (i1 < S) out[i1] = a1;
    }
}

extern "C" void kernel_launch(void* const* d_in, const int* in_sizes, int n_in,
                              void* d_out, int out_size)
{
    const float* lambdas = (const float*)d_in[0];
    const float* kappas  = (const float*)d_in[1];
    const float* thetas  = (const float*)d_in[2];
    const float* phis    = (const float*)d_in[3];
    const float* wi      = (const float*)d_in[4];
    float* out = (float*)d_out;

    int N = in_sizes[0];
    int S = in_sizes[4] / 3;

    int blocks = (S + DIRS_PER_BLOCK - 1) / DIRS_PER_BLOCK;
    vmf_mixture_kernel<<<blocks, BLOCK_THREADS>>>(lambdas, kappas, thetas, phis, wi,
                                                  out, S, N);
}